// round 5
// baseline (speedup 1.0000x reference)
#include <cuda_runtime.h>
#include <cstdint>

#define TT 1024
#define ND (2 * TT - 1)
#define DPAD 2080                     // padded diag count (prefetch overrun room)
#define BN 16
#define BIGS 1e10f

// anti-diagonal-major cost: element (i,j) at [b][(i+j)*TT + i]  (~136 MB)
__device__ float g_diag[(size_t)BN * DPAD * TT];
__device__ float g_sq[2][BN][TT];

__global__ void zero_kernel(float* out) { out[0] = 0.0f; }

__global__ void sq_kernel(const float* __restrict__ x, const float* __restrict__ y) {
    int b = blockIdx.x, w = blockIdx.y, r = threadIdx.x;
    const float* p = (w ? y : x) + ((size_t)(b * TT + r)) * 64;
    float s = 0.0f;
#pragma unroll
    for (int c = 0; c < 64; c += 4) {
        float4 v = *(const float4*)(p + c);
        s += v.x * v.x + v.y * v.y + v.z * v.z + v.w * v.w;
    }
    g_sq[w][b][r] = s;
}

// cost(i,j) = |x_i|^2 + |y_j|^2 - 2 x_i . y_j, diag-major output.
__global__ void __launch_bounds__(256, 2) cost_kernel(const float* __restrict__ x,
                                                      const float* __restrict__ y) {
    __shared__ __align__(16) float sraw[4672];
    float (*Xs)[20]  = (float(*)[20])sraw;
    float (*Yt)[132] = (float(*)[132])(sraw + 2560);
    float (*S)[132]  = (float(*)[132])sraw;

    int b = blockIdx.z, it = blockIdx.y, jt = blockIdx.x;
    int tx = threadIdx.x, ty = threadIdx.y;
    int tid = ty * 16 + tx;

    const float* xb = x + ((size_t)(b * TT + it * 128)) * 64;
    const float* yb = y + ((size_t)(b * TT + jt * 128)) * 64;

    float acc[8][8];
#pragma unroll
    for (int r = 0; r < 8; ++r)
#pragma unroll
        for (int c = 0; c < 8; ++c) acc[r][c] = 0.0f;

    for (int kc = 0; kc < 64; kc += 16) {
#pragma unroll
        for (int q = 0; q < 2; ++q) {
            int idx = tid + q * 256;
            int row = idx >> 2;
            int kq  = (idx & 3) << 2;
            float4 v = *(const float4*)(xb + (size_t)row * 64 + kc + kq);
            *(float4*)&Xs[row][kq] = v;
            float4 w = *(const float4*)(yb + (size_t)row * 64 + kc + kq);
            Yt[kq + 0][row] = w.x;
            Yt[kq + 1][row] = w.y;
            Yt[kq + 2][row] = w.z;
            Yt[kq + 3][row] = w.w;
        }
        __syncthreads();

#pragma unroll
        for (int k4 = 0; k4 < 16; k4 += 4) {
            float4 av[8];
#pragma unroll
            for (int r = 0; r < 8; ++r) av[r] = *(const float4*)&Xs[ty * 8 + r][k4];
#pragma unroll
            for (int kk = 0; kk < 4; ++kk) {
                float4 b0 = *(const float4*)&Yt[k4 + kk][tx * 8];
                float4 b1 = *(const float4*)&Yt[k4 + kk][tx * 8 + 4];
#pragma unroll
                for (int r = 0; r < 8; ++r) {
                    float a = (kk == 0) ? av[r].x : (kk == 1) ? av[r].y
                             : (kk == 2) ? av[r].z : av[r].w;
                    acc[r][0] = fmaf(a, b0.x, acc[r][0]);
                    acc[r][1] = fmaf(a, b0.y, acc[r][1]);
                    acc[r][2] = fmaf(a, b0.z, acc[r][2]);
                    acc[r][3] = fmaf(a, b0.w, acc[r][3]);
                    acc[r][4] = fmaf(a, b1.x, acc[r][4]);
                    acc[r][5] = fmaf(a, b1.y, acc[r][5]);
                    acc[r][6] = fmaf(a, b1.z, acc[r][6]);
                    acc[r][7] = fmaf(a, b1.w, acc[r][7]);
                }
            }
        }
        __syncthreads();
    }

    int r0 = it * 128, c0 = jt * 128;
    int cbase = c0 + tx * 8;
    float y2[8];
#pragma unroll
    for (int c = 0; c < 8; ++c) y2[c] = g_sq[1][b][cbase + c];

    float* gd = g_diag + (size_t)b * DPAD * TT;
    int wid = tid >> 5, lane = tid & 31;

    for (int k = 0; k < 4; ++k) {
        __syncthreads();
        if ((ty >> 2) == k) {
            int rl0 = (ty & 3) * 8;
#pragma unroll
            for (int r = 0; r < 8; ++r) {
                int i = r0 + k * 32 + rl0 + r;
                float x2 = g_sq[0][b][i];
                float4 o0, o1;
                o0.x = x2 + y2[0] - 2.0f * acc[r][0];
                o0.y = x2 + y2[1] - 2.0f * acc[r][1];
                o0.z = x2 + y2[2] - 2.0f * acc[r][2];
                o0.w = x2 + y2[3] - 2.0f * acc[r][3];
                o1.x = x2 + y2[4] - 2.0f * acc[r][4];
                o1.y = x2 + y2[5] - 2.0f * acc[r][5];
                o1.z = x2 + y2[6] - 2.0f * acc[r][6];
                o1.w = x2 + y2[7] - 2.0f * acc[r][7];
                *(float4*)&S[rl0 + r][tx * 8]     = o0;
                *(float4*)&S[rl0 + r][tx * 8 + 4] = o1;
            }
        }
        __syncthreads();
        int i0 = r0 + k * 32;
        int d0 = i0 + c0;
        for (int dl = wid; dl < 32 + 128 - 1; dl += 8) {
            int rl = lane;
            int c  = dl - rl;
            if ((unsigned)c < 128u) {
                gd[(size_t)(d0 + dl) * TT + i0 + rl] = S[rl][c];
            }
        }
    }
}

// Coarsened warp-staircase wavefront DTW: 4 rows per lane held in registers.
// Lane l, row q (i = 128w + 4l + q) at local step t computes column t-4l-q.
// R[i-1,j] for q=1..3 = own previous-step register; q=0 via shfl_up of cur3.
// All 4 costs per step lie on one diagonal -> single float4 LDG.
// Warp w lags warp w-1 by 160 steps; boundary flows through a 128-slot ring,
// ordered by a CTA barrier every 32 steps (producer->consumer gap = 33 > 32).
__global__ void __launch_bounds__(256, 1) dp_kernel(float* __restrict__ out) {
    __shared__ float ring[9][128];      // ring[w] read by warp w; ring[w+1] written
    int b = blockIdx.x;
    int tid = threadIdx.x;
    int w = tid >> 5, l = tid & 31;

    if (tid < 128) ring[0][tid] = BIGS; // boundary "row -1" for warp 0

    float* rin  = ring[w];
    float* rout = ring[w + 1];

    // cost pointer: diag d = 128w + t, rows 128w+4l .. +3  -> float4
    const float* ld = g_diag + ((size_t)b * DPAD + 128 * w) * TT + 128 * w + 4 * l;

    float cur0 = BIGS, cur1 = BIGS, cur2 = BIGS, cur3 = BIGS;
    float Cv0 = (tid == 0) ? 0.0f : BIGS;   // R[-1,-1] = 0 for the very first cell
    float Cv1 = BIGS, Cv2 = BIGS, Cv3 = BIGS;
    float res = 0.0f;
    int   tl  = 0;                          // local step
    int   j0  = -4 * l;                     // column of q=0 at step tl
    bool  p0 = (l == 0), p31 = (l == 31);

    float4 Dq[8];
    int sb = 5 * w;                         // start block (160-step warp skew)
    __syncthreads();

    for (int blk = 0; blk < 71; ++blk) {
        if (blk >= sb && blk < sb + 36) {
            if (blk == sb) {                // prime 8-deep float4 prefetch
#pragma unroll
                for (int q = 0; q < 8; ++q) { Dq[q] = *(const float4*)ld; ld += TT; }
            }
#pragma unroll 8
            for (int k = 0; k < 32; ++k) {
                float4 D = Dq[tl & 7];
                Dq[tl & 7] = *(const float4*)ld;   // prefetch step tl+8
                ld += TT;

                float top = __shfl_up_sync(0xffffffffu, cur3, 1);
                if (p0) top = rin[tl & 127];        // warp w-1 boundary, col tl

                float A0 = top, A1 = cur0, A2 = cur1, A3 = cur2;
                bool v0 = (unsigned)(j0)     < (unsigned)TT;
                bool v1 = (unsigned)(j0 - 1) < (unsigned)TT;
                bool v2 = (unsigned)(j0 - 2) < (unsigned)TT;
                bool v3 = (unsigned)(j0 - 3) < (unsigned)TT;

                float n0 = D.x + fminf(fminf(A0, cur0), Cv0);
                float n1 = D.y + fminf(fminf(A1, cur1), Cv1);
                float n2 = D.z + fminf(fminf(A2, cur2), Cv2);
                float n3 = D.w + fminf(fminf(A3, cur3), Cv3);
                cur0 = v0 ? n0 : BIGS;
                cur1 = v1 ? n1 : BIGS;
                cur2 = v2 ? n2 : BIGS;
                cur3 = v3 ? n3 : BIGS;
                if (v3) res = cur3;                 // last valid = R[row, 1023]

                Cv0 = A0; Cv1 = A1; Cv2 = A2; Cv3 = A3;
                if (p31 && v3) rout[(tl + 1) & 127] = cur3;  // col tl-127
                ++tl; ++j0;
            }
        }
        __syncthreads();
    }

    if (tid == 255) atomicAdd(out, res);    // warp 7 lane 31 row q3 = R[1023,1023]
}

extern "C" void kernel_launch(void* const* d_in, const int* in_sizes, int n_in,
                              void* d_out, int out_size) {
    const float* x = (const float*)d_in[0];
    const float* y = (const float*)d_in[1];
    float* out = (float*)d_out;

    zero_kernel<<<1, 1>>>(out);
    sq_kernel<<<dim3(BN, 2), TT>>>(x, y);
    cost_kernel<<<dim3(8, 8, BN), dim3(16, 16)>>>(x, y);
    dp_kernel<<<BN, 256>>>(out);
}

// round 6
// speedup vs baseline: 1.8482x; 1.8482x over previous
#include <cuda_runtime.h>
#include <cstdint>

#define TT 1024
#define ND (2 * TT - 1)
#define DPAD 2080                     // padded diag count (prefetch overrun room)
#define BN 16
#define BIGS 1e10f

// anti-diagonal-major cost: element (i,j) at [b][(i+j)*TT + i]  (~136 MB)
__device__ float g_diag[(size_t)BN * DPAD * TT];
__device__ float g_sq[2][BN][TT];

__global__ void zero_kernel(float* out) { out[0] = 0.0f; }

__global__ void sq_kernel(const float* __restrict__ x, const float* __restrict__ y) {
    int b = blockIdx.x, w = blockIdx.y, r = threadIdx.x;
    const float* p = (w ? y : x) + ((size_t)(b * TT + r)) * 64;
    float s = 0.0f;
#pragma unroll
    for (int c = 0; c < 64; c += 4) {
        float4 v = *(const float4*)(p + c);
        s += v.x * v.x + v.y * v.y + v.z * v.z + v.w * v.w;
    }
    g_sq[w][b][r] = s;
}

// cost(i,j) = |x_i|^2 + |y_j|^2 - 2 x_i . y_j, diag-major output.
__global__ void __launch_bounds__(256, 2) cost_kernel(const float* __restrict__ x,
                                                      const float* __restrict__ y) {
    __shared__ __align__(16) float sraw[4672];
    float (*Xs)[20]  = (float(*)[20])sraw;
    float (*Yt)[132] = (float(*)[132])(sraw + 2560);
    float (*S)[132]  = (float(*)[132])sraw;

    int b = blockIdx.z, it = blockIdx.y, jt = blockIdx.x;
    int tx = threadIdx.x, ty = threadIdx.y;
    int tid = ty * 16 + tx;

    const float* xb = x + ((size_t)(b * TT + it * 128)) * 64;
    const float* yb = y + ((size_t)(b * TT + jt * 128)) * 64;

    float acc[8][8];
#pragma unroll
    for (int r = 0; r < 8; ++r)
#pragma unroll
        for (int c = 0; c < 8; ++c) acc[r][c] = 0.0f;

    for (int kc = 0; kc < 64; kc += 16) {
#pragma unroll
        for (int q = 0; q < 2; ++q) {
            int idx = tid + q * 256;
            int row = idx >> 2;
            int kq  = (idx & 3) << 2;
            float4 v = *(const float4*)(xb + (size_t)row * 64 + kc + kq);
            *(float4*)&Xs[row][kq] = v;
            float4 w = *(const float4*)(yb + (size_t)row * 64 + kc + kq);
            Yt[kq + 0][row] = w.x;
            Yt[kq + 1][row] = w.y;
            Yt[kq + 2][row] = w.z;
            Yt[kq + 3][row] = w.w;
        }
        __syncthreads();

#pragma unroll
        for (int k4 = 0; k4 < 16; k4 += 4) {
            float4 av[8];
#pragma unroll
            for (int r = 0; r < 8; ++r) av[r] = *(const float4*)&Xs[ty * 8 + r][k4];
#pragma unroll
            for (int kk = 0; kk < 4; ++kk) {
                float4 b0 = *(const float4*)&Yt[k4 + kk][tx * 8];
                float4 b1 = *(const float4*)&Yt[k4 + kk][tx * 8 + 4];
#pragma unroll
                for (int r = 0; r < 8; ++r) {
                    float a = (kk == 0) ? av[r].x : (kk == 1) ? av[r].y
                             : (kk == 2) ? av[r].z : av[r].w;
                    acc[r][0] = fmaf(a, b0.x, acc[r][0]);
                    acc[r][1] = fmaf(a, b0.y, acc[r][1]);
                    acc[r][2] = fmaf(a, b0.z, acc[r][2]);
                    acc[r][3] = fmaf(a, b0.w, acc[r][3]);
                    acc[r][4] = fmaf(a, b1.x, acc[r][4]);
                    acc[r][5] = fmaf(a, b1.y, acc[r][5]);
                    acc[r][6] = fmaf(a, b1.z, acc[r][6]);
                    acc[r][7] = fmaf(a, b1.w, acc[r][7]);
                }
            }
        }
        __syncthreads();
    }

    int r0 = it * 128, c0 = jt * 128;
    int cbase = c0 + tx * 8;
    float y2[8];
#pragma unroll
    for (int c = 0; c < 8; ++c) y2[c] = g_sq[1][b][cbase + c];

    float* gd = g_diag + (size_t)b * DPAD * TT;
    int wid = tid >> 5, lane = tid & 31;

    for (int k = 0; k < 4; ++k) {
        __syncthreads();
        if ((ty >> 2) == k) {
            int rl0 = (ty & 3) * 8;
#pragma unroll
            for (int r = 0; r < 8; ++r) {
                int i = r0 + k * 32 + rl0 + r;
                float x2 = g_sq[0][b][i];
                float4 o0, o1;
                o0.x = x2 + y2[0] - 2.0f * acc[r][0];
                o0.y = x2 + y2[1] - 2.0f * acc[r][1];
                o0.z = x2 + y2[2] - 2.0f * acc[r][2];
                o0.w = x2 + y2[3] - 2.0f * acc[r][3];
                o1.x = x2 + y2[4] - 2.0f * acc[r][4];
                o1.y = x2 + y2[5] - 2.0f * acc[r][5];
                o1.z = x2 + y2[6] - 2.0f * acc[r][6];
                o1.w = x2 + y2[7] - 2.0f * acc[r][7];
                *(float4*)&S[rl0 + r][tx * 8]     = o0;
                *(float4*)&S[rl0 + r][tx * 8 + 4] = o1;
            }
        }
        __syncthreads();
        int i0 = r0 + k * 32;
        int d0 = i0 + c0;
        for (int dl = wid; dl < 32 + 128 - 1; dl += 8) {
            int rl = lane;
            int c  = dl - rl;
            if ((unsigned)c < 128u) {
                gd[(size_t)(d0 + dl) * TT + i0 + rl] = S[rl][c];
            }
        }
    }
}

// Coarsened warp-staircase wavefront DTW: 4 rows per lane in registers.
// Lane l, row q (i = 128w + 4l + q) at local step t computes column t-4l-q.
// R[i-1,j] for q=1..3 = own previous-step register; q=0 via shfl_up of cur3.
// 4 costs per step = one diagonal float4 LDG. Warp skew 160 steps; boundary
// via 128-slot smem ring + CTA barrier every 32 steps (dep gap 33 > 32).
// Prefetch queue Dq uses ONLY unroll-literal indices (k & 7) so it stays in
// registers (R5's tl&7 indexing spilled it to local memory).
__global__ void __launch_bounds__(256, 1) dp_kernel(float* __restrict__ out) {
    __shared__ float ring[9][128];      // ring[w] read by warp w; ring[w+1] written
    int b = blockIdx.x;
    int tid = threadIdx.x;
    int w = tid >> 5, l = tid & 31;

    if (tid < 128) ring[0][tid] = BIGS; // boundary "row -1" for warp 0

    float* rin  = ring[w];
    float* rout = ring[w + 1];

    // cost pointer: diag d = 128w + t, rows 128w+4l .. +3  -> float4
    const float* ld = g_diag + ((size_t)b * DPAD + 128 * w) * TT + 128 * w + 4 * l;

    float cur0 = BIGS, cur1 = BIGS, cur2 = BIGS, cur3 = BIGS;
    float Cv0 = (tid == 0) ? 0.0f : BIGS;   // R[-1,-1] = 0 seeds the first cell
    float Cv1 = BIGS, Cv2 = BIGS, Cv3 = BIGS;
    float res = 0.0f;
    int   tl  = 0;                          // local step (ring index / valid base)
    int   j0  = -4 * l;                     // column of q=0 at step tl
    bool  p0 = (l == 0), p31 = (l == 31);

    float4 Dq[8];
    int sb = 5 * w;                         // start block (160-step warp skew)
    __syncthreads();

    for (int blk = 0; blk < 71; ++blk) {
        if (blk >= sb && blk < sb + 36) {
            if (blk == sb) {                // prime 8-deep float4 prefetch
#pragma unroll
                for (int q = 0; q < 8; ++q) { Dq[q] = *(const float4*)ld; ld += TT; }
            }
#pragma unroll
            for (int k = 0; k < 32; ++k) { // full unroll: Dq indices all literal
                float4 D = Dq[k & 7];
                Dq[k & 7] = *(const float4*)ld;    // prefetch step tl+8
                ld += TT;

                float top = __shfl_up_sync(0xffffffffu, cur3, 1);
                if (p0) top = rin[tl & 127];        // warp w-1 boundary, col tl

                float A0 = top, A1 = cur0, A2 = cur1, A3 = cur2;
                bool v0 = (unsigned)(j0)     < (unsigned)TT;
                bool v1 = (unsigned)(j0 - 1) < (unsigned)TT;
                bool v2 = (unsigned)(j0 - 2) < (unsigned)TT;
                bool v3 = (unsigned)(j0 - 3) < (unsigned)TT;

                float n0 = D.x + fminf(fminf(A0, cur0), Cv0);
                float n1 = D.y + fminf(fminf(A1, cur1), Cv1);
                float n2 = D.z + fminf(fminf(A2, cur2), Cv2);
                float n3 = D.w + fminf(fminf(A3, cur3), Cv3);
                cur0 = v0 ? n0 : BIGS;
                cur1 = v1 ? n1 : BIGS;
                cur2 = v2 ? n2 : BIGS;
                cur3 = v3 ? n3 : BIGS;
                if (v3) res = cur3;                 // last valid = R[row, 1023]

                Cv0 = A0; Cv1 = A1; Cv2 = A2; Cv3 = A3;
                if (p31 && v3) rout[(tl + 1) & 127] = cur3;  // col tl-127
                ++tl; ++j0;
            }
        }
        __syncthreads();
    }

    if (tid == 255) atomicAdd(out, res);    // warp 7 lane 31 row q3 = R[1023,1023]
}

extern "C" void kernel_launch(void* const* d_in, const int* in_sizes, int n_in,
                              void* d_out, int out_size) {
    const float* x = (const float*)d_in[0];
    const float* y = (const float*)d_in[1];
    float* out = (float*)d_out;

    zero_kernel<<<1, 1>>>(out);
    sq_kernel<<<dim3(BN, 2), TT>>>(x, y);
    cost_kernel<<<dim3(8, 8, BN), dim3(16, 16)>>>(x, y);
    dp_kernel<<<BN, 256>>>(out);
}